// round 7
// baseline (speedup 1.0000x reference)
#include <cuda_runtime.h>
#include <cstdint>

// Problem constants (from reference)
#define N_NODES 2000000
#define N_EDGES 32000000
#define N_OUT   400000   // N_NODES / 5

#define EDGES_PER_THREAD 16

// Aggregation slots only for nodes with idx % 5 == 0 (1.6 MB, L2-resident).
// Zero-initialized at module load; finalize_kernel re-zeros it each replay.
__device__ float g_agg[N_OUT];

// --------------------------------------------------------------------------
// Scatter: edge_index is int32. Stream dst (filter %5) with evict-first
// (__ldcs) so the streams don't evict the 8 MB x table from L2; gather
// x[src] (L2 hit) and RED into g_agg[dst/5]. 16 edges/thread; src int4s
// loaded only if any of their 4 dsts pass the filter.
// --------------------------------------------------------------------------
__global__ void scatter_kernel(const float* __restrict__ x,
                               const int* __restrict__ src,
                               const int* __restrict__ dst) {
    long long base = (long long)(blockIdx.x * (long long)blockDim.x + threadIdx.x)
                     * EDGES_PER_THREAD;
    if (base >= N_EDGES) return;

    // Batch all dst loads first (MLP_p1 = 4, streaming / evict-first)
    int4 dv[4];
#pragma unroll
    for (int v = 0; v < 4; v++)
        dv[v] = __ldcs(reinterpret_cast<const int4*>(dst + base + v * 4));

#pragma unroll
    for (int v = 0; v < 4; v++) {
        int d[4] = { dv[v].x, dv[v].y, dv[v].z, dv[v].w };
        bool m0 = (d[0] % 5 == 0);
        bool m1 = (d[1] % 5 == 0);
        bool m2 = (d[2] % 5 == 0);
        bool m3 = (d[3] % 5 == 0);
        if (m0 | m1 | m2 | m3) {
            int4 sv = __ldcs(reinterpret_cast<const int4*>(src + base + v * 4));
            int s[4] = { sv.x, sv.y, sv.z, sv.w };
            if (m0) atomicAdd(&g_agg[d[0] / 5], __ldg(x + s[0]));
            if (m1) atomicAdd(&g_agg[d[1] / 5], __ldg(x + s[1]));
            if (m2) atomicAdd(&g_agg[d[2] / 5], __ldg(x + s[2]));
            if (m3) atomicAdd(&g_agg[d[3] / 5], __ldg(x + s[3]));
        }
    }
}

// --------------------------------------------------------------------------
// Finalize: a = agg*w_conv + b_conv; collapsed scalar MLP; write out.
// Also resets g_agg to 0 for the next graph replay (replaces zero kernel).
// --------------------------------------------------------------------------
__global__ void finalize_kernel(const float* __restrict__ w_conv,
                                const float* __restrict__ b_conv,
                                const float* __restrict__ w1,
                                const float* __restrict__ b1,
                                const float* __restrict__ w2,
                                const float* __restrict__ b2,
                                float* __restrict__ out) {
    int i = blockIdx.x * blockDim.x + threadIdx.x;
    if (i >= N_OUT) return;

    float agg = g_agg[i];
    g_agg[i] = 0.0f;                       // reset for next replay

    float a = fmaf(agg, __ldg(w_conv), __ldg(b_conv));

    float acc = __ldg(b2);
#pragma unroll
    for (int j = 0; j < 4; j++) {
        // w1 stored [in=2, out=4] row-major: row0 then row1
        float weff = __ldg(w1 + j) + __ldg(w1 + 4 + j);
        float t = fmaxf(fmaf(a, weff, __ldg(b1 + j)), 0.0f);
        acc = fmaf(t, __ldg(w2 + j), acc);
    }
    out[i] = acc;
}

// --------------------------------------------------------------------------
// Launch
// inputs per metadata order:
//   d_in[0] x          (2,000,000 f32)
//   d_in[1] edge_index (2 x 32,000,000 int32, row-major: src row then dst row)
//   d_in[2] w_conv (1)  d_in[3] b_conv (1)
//   d_in[4] w1 (8)      d_in[5] b1 (4)
//   d_in[6] w2 (4)      d_in[7] b2 (1)
// output: 400,000 f32
// --------------------------------------------------------------------------
extern "C" void kernel_launch(void* const* d_in, const int* in_sizes, int n_in,
                              void* d_out, int out_size) {
    const float* x   = (const float*)d_in[0];
    const int*   ei  = (const int*)d_in[1];
    const int*   src = ei;
    const int*   dst = ei + N_EDGES;
    const float* w_conv = (const float*)d_in[2];
    const float* b_conv = (const float*)d_in[3];
    const float* w1     = (const float*)d_in[4];
    const float* b1     = (const float*)d_in[5];
    const float* w2     = (const float*)d_in[6];
    const float* b2     = (const float*)d_in[7];
    float* out = (float*)d_out;

    {
        int threads = 256;
        long long work = (long long)N_EDGES / EDGES_PER_THREAD;   // 2M threads
        int blocks = (int)((work + threads - 1) / threads);       // 7813
        scatter_kernel<<<blocks, threads>>>(x, src, dst);
    }
    {
        int threads = 256;
        int blocks = (N_OUT + threads - 1) / threads;
        finalize_kernel<<<blocks, threads>>>(w_conv, b_conv, w1, b1, w2, b2, out);
    }
}

// round 8
// speedup vs baseline: 1.0964x; 1.0964x over previous
#include <cuda_runtime.h>
#include <cstdint>

// Problem constants (from reference)
#define N_NODES 2000000
#define N_EDGES 32000000
#define N_OUT   400000   // N_NODES / 5

#define EDGES_PER_THREAD 8

// Aggregation slots only for nodes with idx % 5 == 0 (1.6 MB, L2-resident).
// Zero-initialized at module load; finalize_kernel re-zeros it each replay.
__device__ float g_agg[N_OUT];

// --------------------------------------------------------------------------
// Scatter: edge_index is int32. All stream loads (2x dst int4, 2x src int4)
// issued unconditionally, back-to-back at the top of the thread (MLP_p1=4),
// with __ldcs (evict-first) so the 256 MB edge stream doesn't evict the
// 8 MB x table from L2. Then filter %5, gather x[src] (L2 hit), RED into
// g_agg[dst/5].
// --------------------------------------------------------------------------
__global__ void scatter_kernel(const float* __restrict__ x,
                               const int* __restrict__ src,
                               const int* __restrict__ dst) {
    long long base = (long long)(blockIdx.x * (long long)blockDim.x + threadIdx.x)
                     * EDGES_PER_THREAD;
    if (base >= N_EDGES) return;

    // Front-batch ALL stream loads: 4 independent 16B LDGs in flight.
    int4 dv0 = __ldcs(reinterpret_cast<const int4*>(dst + base));
    int4 dv1 = __ldcs(reinterpret_cast<const int4*>(dst + base + 4));
    int4 sv0 = __ldcs(reinterpret_cast<const int4*>(src + base));
    int4 sv1 = __ldcs(reinterpret_cast<const int4*>(src + base + 4));

    int d[8] = { dv0.x, dv0.y, dv0.z, dv0.w, dv1.x, dv1.y, dv1.z, dv1.w };
    int s[8] = { sv0.x, sv0.y, sv0.z, sv0.w, sv1.x, sv1.y, sv1.z, sv1.w };

#pragma unroll
    for (int k = 0; k < 8; k++) {
        if (d[k] % 5 == 0) {
            float v = __ldg(x + s[k]);            // x[src] — L2-resident gather
            atomicAdd(&g_agg[d[k] / 5], v);       // no return -> REDG to L2
        }
    }
}

// --------------------------------------------------------------------------
// Finalize: a = agg*w_conv + b_conv; collapsed scalar MLP; write out.
// Also resets g_agg to 0 for the next graph replay (replaces zero kernel).
// --------------------------------------------------------------------------
__global__ void finalize_kernel(const float* __restrict__ w_conv,
                                const float* __restrict__ b_conv,
                                const float* __restrict__ w1,
                                const float* __restrict__ b1,
                                const float* __restrict__ w2,
                                const float* __restrict__ b2,
                                float* __restrict__ out) {
    int i = blockIdx.x * blockDim.x + threadIdx.x;
    if (i >= N_OUT) return;

    float agg = g_agg[i];
    g_agg[i] = 0.0f;                       // reset for next replay

    float a = fmaf(agg, __ldg(w_conv), __ldg(b_conv));

    float acc = __ldg(b2);
#pragma unroll
    for (int j = 0; j < 4; j++) {
        // w1 stored [in=2, out=4] row-major: row0 then row1
        float weff = __ldg(w1 + j) + __ldg(w1 + 4 + j);
        float t = fmaxf(fmaf(a, weff, __ldg(b1 + j)), 0.0f);
        acc = fmaf(t, __ldg(w2 + j), acc);
    }
    out[i] = acc;
}

// --------------------------------------------------------------------------
// Launch
// inputs per metadata order:
//   d_in[0] x          (2,000,000 f32)
//   d_in[1] edge_index (2 x 32,000,000 int32, row-major: src row then dst row)
//   d_in[2] w_conv (1)  d_in[3] b_conv (1)
//   d_in[4] w1 (8)      d_in[5] b1 (4)
//   d_in[6] w2 (4)      d_in[7] b2 (1)
// output: 400,000 f32
// --------------------------------------------------------------------------
extern "C" void kernel_launch(void* const* d_in, const int* in_sizes, int n_in,
                              void* d_out, int out_size) {
    const float* x   = (const float*)d_in[0];
    const int*   ei  = (const int*)d_in[1];
    const int*   src = ei;
    const int*   dst = ei + N_EDGES;
    const float* w_conv = (const float*)d_in[2];
    const float* b_conv = (const float*)d_in[3];
    const float* w1     = (const float*)d_in[4];
    const float* b1     = (const float*)d_in[5];
    const float* w2     = (const float*)d_in[6];
    const float* b2     = (const float*)d_in[7];
    float* out = (float*)d_out;

    {
        int threads = 256;
        long long work = (long long)N_EDGES / EDGES_PER_THREAD;   // 4M threads
        int blocks = (int)((work + threads - 1) / threads);       // 15625
        scatter_kernel<<<blocks, threads>>>(x, src, dst);
    }
    {
        int threads = 256;
        int blocks = (N_OUT + threads - 1) / threads;
        finalize_kernel<<<blocks, threads>>>(w_conv, b_conv, w1, b1, w2, b2, out);
    }
}

// round 9
// speedup vs baseline: 1.2208x; 1.1135x over previous
#include <cuda_runtime.h>
#include <cstdint>

// Problem constants (from reference)
#define N_NODES 2000000
#define N_EDGES 32000000
#define N_OUT   400000   // N_NODES / 5

// Aggregation slots only for nodes with idx % 5 == 0 (1.6 MB, L2-resident).
// Zero-initialized at module load; finalize_kernel re-zeros it each replay.
__device__ float g_agg[N_OUT];

// --------------------------------------------------------------------------
// Scatter (exact R2 structure — measured best at 76.5 total):
// 4 edges/thread, 8M threads, plain __ldg int4 loads for both streams,
// filter dst % 5, gather x[src], RED into g_agg[dst/5].
// --------------------------------------------------------------------------
__global__ void scatter_kernel(const float* __restrict__ x,
                               const int* __restrict__ src,
                               const int* __restrict__ dst) {
    long long base = (long long)(blockIdx.x * (long long)blockDim.x + threadIdx.x) * 4;
    if (base >= N_EDGES) return;

    int4 dv = *reinterpret_cast<const int4*>(dst + base);
    int4 sv = *reinterpret_cast<const int4*>(src + base);

    int d[4] = { dv.x, dv.y, dv.z, dv.w };
    int s[4] = { sv.x, sv.y, sv.z, sv.w };

#pragma unroll
    for (int k = 0; k < 4; k++) {
        if (d[k] % 5 == 0) {
            float v = __ldg(x + s[k]);            // x[src] — L2 gather
            atomicAdd(&g_agg[d[k] / 5], v);       // no return -> REDG to L2
        }
    }
}

// --------------------------------------------------------------------------
// Finalize: a = agg*w_conv + b_conv; collapsed scalar MLP; write out.
// Also resets g_agg to 0 for the next graph replay (replaces zero kernel).
// --------------------------------------------------------------------------
__global__ void finalize_kernel(const float* __restrict__ w_conv,
                                const float* __restrict__ b_conv,
                                const float* __restrict__ w1,
                                const float* __restrict__ b1,
                                const float* __restrict__ w2,
                                const float* __restrict__ b2,
                                float* __restrict__ out) {
    int i = blockIdx.x * blockDim.x + threadIdx.x;
    if (i >= N_OUT) return;

    float agg = g_agg[i];
    g_agg[i] = 0.0f;                       // reset for next replay

    float a = fmaf(agg, __ldg(w_conv), __ldg(b_conv));

    float acc = __ldg(b2);
#pragma unroll
    for (int j = 0; j < 4; j++) {
        // w1 stored [in=2, out=4] row-major: row0 then row1
        float weff = __ldg(w1 + j) + __ldg(w1 + 4 + j);
        float t = fmaxf(fmaf(a, weff, __ldg(b1 + j)), 0.0f);
        acc = fmaf(t, __ldg(w2 + j), acc);
    }
    out[i] = acc;
}

// --------------------------------------------------------------------------
// Launch
// inputs per metadata order:
//   d_in[0] x          (2,000,000 f32)
//   d_in[1] edge_index (2 x 32,000,000 int32, row-major: src row then dst row)
//   d_in[2] w_conv (1)  d_in[3] b_conv (1)
//   d_in[4] w1 (8)      d_in[5] b1 (4)
//   d_in[6] w2 (4)      d_in[7] b2 (1)
// output: 400,000 f32
// --------------------------------------------------------------------------
extern "C" void kernel_launch(void* const* d_in, const int* in_sizes, int n_in,
                              void* d_out, int out_size) {
    const float* x   = (const float*)d_in[0];
    const int*   ei  = (const int*)d_in[1];
    const int*   src = ei;
    const int*   dst = ei + N_EDGES;
    const float* w_conv = (const float*)d_in[2];
    const float* b_conv = (const float*)d_in[3];
    const float* w1     = (const float*)d_in[4];
    const float* b1     = (const float*)d_in[5];
    const float* w2     = (const float*)d_in[6];
    const float* b2     = (const float*)d_in[7];
    float* out = (float*)d_out;

    {
        int threads = 256;
        long long work = (long long)N_EDGES / 4;            // 8M threads, 4 edges each
        int blocks = (int)((work + threads - 1) / threads); // 31250
        scatter_kernel<<<blocks, threads>>>(x, src, dst);
    }
    {
        int threads = 256;
        int blocks = (N_OUT + threads - 1) / threads;
        finalize_kernel<<<blocks, threads>>>(w_conv, b_conv, w1, b1, w2, b2, out);
    }
}

// round 10
// speedup vs baseline: 1.2268x; 1.0049x over previous
#include <cuda_runtime.h>
#include <cstdint>

// Problem constants (from reference)
#define N_NODES 2000000
#define N_EDGES 32000000
#define N_OUT   400000   // N_NODES / 5
#define N_OUT4  100000   // N_OUT / 4

// Aggregation slots only for nodes with idx % 5 == 0 (1.6 MB, L2-resident).
// Declared as float4 for 16B-aligned vector access in finalize; scatter
// addresses it through a scalar float view. Zero-initialized at module load;
// finalize re-zeros it each replay.
__device__ float4 g_agg4[N_OUT4];

// --------------------------------------------------------------------------
// Scatter (frozen at R8 measured-best structure):
// 4 edges/thread, 8M threads, plain __ldg int4 loads for both streams,
// filter dst % 5, gather x[src], RED into agg[dst/5].
// --------------------------------------------------------------------------
__global__ void scatter_kernel(const float* __restrict__ x,
                               const int* __restrict__ src,
                               const int* __restrict__ dst) {
    float* agg = reinterpret_cast<float*>(g_agg4);
    long long base = (long long)(blockIdx.x * (long long)blockDim.x + threadIdx.x) * 4;
    if (base >= N_EDGES) return;

    int4 dv = *reinterpret_cast<const int4*>(dst + base);
    int4 sv = *reinterpret_cast<const int4*>(src + base);

    int d[4] = { dv.x, dv.y, dv.z, dv.w };
    int s[4] = { sv.x, sv.y, sv.z, sv.w };

#pragma unroll
    for (int k = 0; k < 4; k++) {
        if (d[k] % 5 == 0) {
            float v = __ldg(x + s[k]);            // x[src] — L2 gather
            atomicAdd(&agg[d[k] / 5], v);         // no return -> REDG to L2
        }
    }
}

// --------------------------------------------------------------------------
// Finalize (vectorized 4x): load float4 of agg, reset to zero for the next
// replay, run the collapsed scalar MLP per component, store float4 out.
// --------------------------------------------------------------------------
__global__ void finalize_kernel(const float* __restrict__ w_conv,
                                const float* __restrict__ b_conv,
                                const float* __restrict__ w1,
                                const float* __restrict__ b1,
                                const float* __restrict__ w2,
                                const float* __restrict__ b2,
                                float4* __restrict__ out) {
    int i = blockIdx.x * blockDim.x + threadIdx.x;
    if (i >= N_OUT4) return;

    float4 aggv = g_agg4[i];
    g_agg4[i] = make_float4(0.0f, 0.0f, 0.0f, 0.0f);   // reset for next replay

    float wc = __ldg(w_conv);
    float bc = __ldg(b_conv);

    // Collapsed MLP coefficients (8 fp32 params, broadcast hits)
    float weff[4], bb1[4], ww2[4];
#pragma unroll
    for (int j = 0; j < 4; j++) {
        weff[j] = __ldg(w1 + j) + __ldg(w1 + 4 + j);   // w1 is [in=2, out=4]
        bb1[j]  = __ldg(b1 + j);
        ww2[j]  = __ldg(w2 + j);
    }
    float bb2 = __ldg(b2);

    float a[4] = { aggv.x, aggv.y, aggv.z, aggv.w };
    float r[4];
#pragma unroll
    for (int e = 0; e < 4; e++) {
        float av = fmaf(a[e], wc, bc);
        float acc = bb2;
#pragma unroll
        for (int j = 0; j < 4; j++) {
            float t = fmaxf(fmaf(av, weff[j], bb1[j]), 0.0f);
            acc = fmaf(t, ww2[j], acc);
        }
        r[e] = acc;
    }
    out[i] = make_float4(r[0], r[1], r[2], r[3]);
}

// --------------------------------------------------------------------------
// Launch
// inputs per metadata order:
//   d_in[0] x          (2,000,000 f32)
//   d_in[1] edge_index (2 x 32,000,000 int32, row-major: src row then dst row)
//   d_in[2] w_conv (1)  d_in[3] b_conv (1)
//   d_in[4] w1 (8)      d_in[5] b1 (4)
//   d_in[6] w2 (4)      d_in[7] b2 (1)
// output: 400,000 f32
// --------------------------------------------------------------------------
extern "C" void kernel_launch(void* const* d_in, const int* in_sizes, int n_in,
                              void* d_out, int out_size) {
    const float* x   = (const float*)d_in[0];
    const int*   ei  = (const int*)d_in[1];
    const int*   src = ei;
    const int*   dst = ei + N_EDGES;
    const float* w_conv = (const float*)d_in[2];
    const float* b_conv = (const float*)d_in[3];
    const float* w1     = (const float*)d_in[4];
    const float* b1     = (const float*)d_in[5];
    const float* w2     = (const float*)d_in[6];
    const float* b2     = (const float*)d_in[7];
    float4* out = (float4*)d_out;

    {
        int threads = 256;
        long long work = (long long)N_EDGES / 4;            // 8M threads, 4 edges each
        int blocks = (int)((work + threads - 1) / threads); // 31250
        scatter_kernel<<<blocks, threads>>>(x, src, dst);
    }
    {
        int threads = 256;
        int blocks = (N_OUT4 + threads - 1) / threads;      // 391
        finalize_kernel<<<blocks, threads>>>(w_conv, b_conv, w1, b1, w2, b2, out);
    }
}